// round 17
// baseline (speedup 1.0000x reference)
#include <cuda_runtime.h>
#include <cuda_bf16.h>
#include <cuda_fp16.h>
#include <cstdint>

#define SEQ       128
#define BATCH     64
#define EMBED     512
#define HDIM      1024
#define NG        4096
#define TSTEPS    127
#define SEL_START 65
#define SEL_COUNT 62
#define MPAD      8192
#define NCTA      128

// ---------------- device scratch ----------------
__device__ __half g_Xh[MPAD * EMBED];          // fp16 embeddings (t-major, padded rows)
__device__ __half g_Wih[NG * EMBED];           // fp16 w_ih, gate-interleaved rows
__device__ __half g_Whh[NG * HDIM];            // fp16 w_hh, gate-interleaved rows
__device__ float g_bsum[NG];
__device__ __half g_h2[2 * BATCH * HDIM];      // ping-pong h (fp16)
__device__ unsigned g_cnt[8][32];              // [quarter*2+half], 128B-spaced
__device__ int g_is64;

// ---------------- smem layout for lstm_persist (bytes) ----------------
#define OFF_H    0        // [32][1032] fp16 = 66048 (also Whh staging pre-loop)
#define OFF_PART 66048    // gate partials [4][32][68] f32 = 34816
#define OFF_PS   100864   // 2 x [32][64] f32 = 16384
#define OFF_WIH  117248   // Wih slice [64][520] fp16 = 66560
#define OFF_X    183808   // X tile [32][520] fp16 / P-partials [4][32][68] f32 = 34816
#define OFF_BS   218624   // bsum[64] f32 = 256
#define SMEM_PERSIST 218880

// ---------------- helpers ----------------
__device__ __forceinline__ void mma16816h(float* c, const uint32_t* a, const uint32_t* b) {
    asm volatile(
        "mma.sync.aligned.m16n8k16.row.col.f32.f16.f16.f32 "
        "{%0,%1,%2,%3}, {%4,%5,%6,%7}, {%8,%9}, {%0,%1,%2,%3};\n"
        : "+f"(c[0]), "+f"(c[1]), "+f"(c[2]), "+f"(c[3])
        : "r"(a[0]), "r"(a[1]), "r"(a[2]), "r"(a[3]), "r"(b[0]), "r"(b[1]));
}
__device__ __forceinline__ void ldsm4(uint32_t* r, uint32_t saddr) {
    asm volatile("ldmatrix.sync.aligned.m8n8.x4.shared.b16 {%0,%1,%2,%3}, [%4];"
        : "=r"(r[0]), "=r"(r[1]), "=r"(r[2]), "=r"(r[3]) : "r"(saddr));
}
__device__ __forceinline__ uint32_t sptr(const void* p) {
    return (uint32_t)__cvta_generic_to_shared(p);
}
__device__ __forceinline__ void cpa16(void* smem, const void* g) {
    uint32_t s = sptr(smem);
    asm volatile("cp.async.cg.shared.global [%0], [%1], 16;\n" :: "r"(s), "l"(g));
}
__device__ __forceinline__ void cpa_commit() { asm volatile("cp.async.commit_group;\n"); }
__device__ __forceinline__ void cpa_wait2()  { asm volatile("cp.async.wait_group 2;\n"); }
__device__ __forceinline__ void cpa_wait1()  { asm volatile("cp.async.wait_group 1;\n"); }
__device__ __forceinline__ void cpa_wait0()  { asm volatile("cp.async.wait_group 0;\n"); }
__device__ __forceinline__ unsigned ldacq(const unsigned* p) {
    unsigned v;
    asm volatile("ld.acquire.gpu.global.u32 %0, [%1];" : "=r"(v) : "l"(p) : "memory");
    return v;
}
__device__ __forceinline__ float ex2f(float x) {
    float y; asm("ex2.approx.f32 %0, %1;" : "=f"(y) : "f"(x)); return y;
}
__device__ __forceinline__ uint32_t ex2h2(uint32_t x) {
    uint32_t y; asm("ex2.approx.f16x2 %0, %1;" : "=r"(y) : "r"(x)); return y;
}
__device__ __forceinline__ float rcpf(float x) {
    float y; asm("rcp.approx.f32 %0, %1;" : "=f"(y) : "f"(x)); return y;
}
#define L2E  1.4426950408889634f
#define L2E2 2.8853900817779268f

// ---------------- fused init (detect + h0 + out + counters) ----------------
__global__ void fused_init(const int* __restrict__ prob32, const float* __restrict__ h0,
                           float* __restrict__ out, const float* __restrict__ b_ans) {
    int bid = blockIdx.x;
    if (bid == 0) {
        __shared__ int any;
        if (threadIdx.x == 0) any = 0;
        __syncthreads();
        int local = 0;
        for (int i = 2 * threadIdx.x + 1; i < BATCH * SEQ; i += 2 * blockDim.x)
            local |= prob32[i];
        if (local) atomicOr(&any, 1);
        __syncthreads();
        if (threadIdx.x == 0) g_is64 = (any == 0) ? 1 : 0;
        if (threadIdx.x < 8) g_cnt[threadIdx.x][0] = 0u;
    } else if (bid <= 64) {
        int i = (bid - 1) * 1024 + threadIdx.x;
        g_h2[i] = __float2half_rn(h0[i]);
    } else {
        int i = (bid - 65) * 1024 + threadIdx.x;
        if (i < BATCH * SEL_COUNT) out[i] = b_ans[0];
    }
}

// ---------------- merged prep: gather + weight conversion ----------------
__global__ void prep_all(const void* __restrict__ prob, const float* __restrict__ table,
                         const float* __restrict__ w_ih, const float* __restrict__ w_hh,
                         const float* __restrict__ b_ih, const float* __restrict__ b_hh) {
    int bid = blockIdx.x;
    int tid = threadIdx.x;
    if (bid < NG) {                       // w_ih -> fp16 (gate-interleaved)
        int n = bid;
        int j = n >> 2, g = n & 3;
        int r = g * HDIM + j;
        if (tid < 128) {
            float4 v = ((const float4*)(w_ih + (size_t)r * EMBED))[tid];
            int o = n * EMBED + tid * 4;
            g_Wih[o + 0] = __float2half_rn(v.x);
            g_Wih[o + 1] = __float2half_rn(v.y);
            g_Wih[o + 2] = __float2half_rn(v.z);
            g_Wih[o + 3] = __float2half_rn(v.w);
        }
        if (tid == 0) g_bsum[n] = b_ih[r] + b_hh[r];
    } else if (bid < 2 * NG) {            // w_hh -> fp16 (gate-interleaved)
        int n = bid - NG;
        int j = n >> 2, g = n & 3;
        int r = g * HDIM + j;
        float4 v = ((const float4*)(w_hh + (size_t)r * HDIM))[tid];
        int o = n * HDIM + tid * 4;
        g_Whh[o + 0] = __float2half_rn(v.x);
        g_Whh[o + 1] = __float2half_rn(v.y);
        g_Whh[o + 2] = __float2half_rn(v.z);
        g_Whh[o + 3] = __float2half_rn(v.w);
    } else {                              // gather: 2 rows per block
        int row = (bid - 2 * NG) * 2 + (tid >> 7);
        if (row < TSTEPS * BATCH) {
            int t = row >> 6, b = row & 63;
            long long tok;
            if (g_is64) tok = ((const long long*)prob)[b * SEQ + t];
            else        tok = (long long)((const int*)prob)[b * SEQ + t];
            int lt = tid & 127;
            float4 v = ((const float4*)(table + (size_t)tok * EMBED))[lt];
            int o = row * EMBED + lt * 4;
            g_Xh[o + 0] = __float2half_rn(v.x);
            g_Xh[o + 1] = __float2half_rn(v.y);
            g_Xh[o + 2] = __float2half_rn(v.z);
            g_Xh[o + 3] = __float2half_rn(v.w);
        }
    }
}

// ---------------- persistent recurrent kernel -----------------------------
// 128 CTAs = 64 col-groups x 2 batch-halves. Fuses the P pre-GEMM into the
// recurrence: P(t+1) slice computed in-loop inside the h-load latency window.
__global__ __launch_bounds__(256, 1)
void lstm_persist(const float* __restrict__ c0, const float* __restrict__ w_ans,
                  float* __restrict__ out) {
    extern __shared__ char smc[];
    const int tid = threadIdx.x, warp = tid >> 5, lane = tid & 31;
    const int gid = lane >> 2, kb = (lane & 3) << 1;
    const int kq = warp >> 1;             // 0..3 K quarter
    const int nh = warp & 1;              // 0..1 N half (32 cols)
    const int cg = blockIdx.x >> 1;       // column group 0..63
    const int bh = blockIdx.x & 1;        // batch half
    const int n0 = cg << 6;               // 64 gate cols
    const int j0 = cg << 4;               // 16 j's
    const int b0 = bh << 5;               // 32 batch rows
    const int a_r = (lane & 7) + (lane & 8);
    const int a_c = (lane & 16) >> 1;
    const int b_r = (lane & 7) + ((lane & 16) >> 1);
    const int b_c = (lane & 8);
    const int grp_c = kq * 2 + bh;            // counter this warp consumes
    const int grp_p = (cg >> 4) * 2 + bh;     // counter this CTA produces

    float* part = (float*)(smc + OFF_PART);   // gate partials [4][32][68]
    float* partP = (float*)(smc + OFF_X);     // P partials (X overlay)
    float* bs   = (float*)(smc + OFF_BS);

    // ---- stage Whh (64 cols x 1024) through h region, two 32-col passes ----
    uint32_t Breg[16][8];
#pragma unroll
    for (int st = 0; st < 2; st++) {
#pragma unroll
        for (int it = 0; it < 16; it++) {
            int op = it * 256 + tid;          // 0..4095
            int r = op >> 7, c = op & 127;
            cpa16(smc + OFF_H + (size_t)r * 2064 + c * 16,
                  g_Whh + (size_t)(n0 + st * 32 + r) * HDIM + c * 8);
        }
        cpa_commit(); cpa_wait0();
        __syncthreads();
        if (nh == st) {
            uint32_t sW = sptr(smc + OFF_H) + (uint32_t)(b_r * 2064) + (uint32_t)b_c * 2;
#pragma unroll
            for (int kf = 0; kf < 16; kf++) {
                uint32_t koff = (uint32_t)(kq * 256 + kf * 16) * 2;
                ldsm4(&Breg[kf][0], sW + koff);
                ldsm4(&Breg[kf][4], sW + 16u * 2064 + koff);
            }
        }
        __syncthreads();
    }

    // ---- load Wih slice (64 x 512 fp16) + bsum ----
#pragma unroll
    for (int it = 0; it < 16; it++) {
        int op = it * 256 + tid;              // 0..4095
        int r = op >> 6, c = op & 63;
        cpa16(smc + OFF_WIH + (size_t)r * 1040 + c * 16,
              g_Wih + (size_t)(n0 + r) * EMBED + c * 8);
    }
    cpa_commit();
    if (tid < 64) bs[tid] = g_bsum[n0 + tid];
    cpa_wait0();
    __syncthreads();

    // ---- per-thread state in registers ----
    float c_reg[2], was_reg[2];
#pragma unroll
    for (int half = 0; half < 2; half++) {
        int idx = tid + half * 256;
        int b = idx >> 4, jj = idx & 15;
        c_reg[half]   = c0[(size_t)(b0 + b) * HDIM + j0 + jj];
        was_reg[half] = w_ans[j0 + jj];
    }

    const uint32_t sAB = sptr(smc + OFF_H)   + (uint32_t)(a_r * 2064) + (uint32_t)a_c * 2;
    const uint32_t sXA = sptr(smc + OFF_X)   + (uint32_t)(a_r * 1040) + (uint32_t)a_c * 2;
    const uint32_t sWI = sptr(smc + OFF_WIH) + (uint32_t)((nh * 32 + b_r) * 1040) + (uint32_t)b_c * 2;

    // ---- helpers as macro-like lambdas ----
    auto load_X = [&](int tt) {
#pragma unroll
        for (int it = 0; it < 8; it++) {
            int idx = it * 256 + tid;         // 0..2047
            int r = idx >> 6, c = idx & 63;
            cpa16(smc + OFF_X + (size_t)r * 1040 + c * 16,
                  g_Xh + ((size_t)tt * BATCH + b0 + r) * EMBED + c * 8);
        }
        cpa_commit();
    };
    auto pmma_store = [&]() {       // P-MMA on X (after X ready + syncthreads by caller)
        float pacc[2][4][4];
#pragma unroll
        for (int a = 0; a < 2; a++)
#pragma unroll
            for (int b = 0; b < 4; b++)
#pragma unroll
                for (int q = 0; q < 4; q++) pacc[a][b][q] = 0.0f;
#pragma unroll
        for (int kf = 0; kf < 8; kf++) {
            uint32_t koff = (uint32_t)(kq * 128 + kf * 16) * 2;
            uint32_t ah[2][4], bf[8];
            ldsm4(ah[0], sXA + koff);
            ldsm4(ah[1], sXA + 16u * 1040 + koff);
            ldsm4(&bf[0], sWI + koff);
            ldsm4(&bf[4], sWI + 16u * 1040 + koff);
#pragma unroll
            for (int mf = 0; mf < 2; mf++)
#pragma unroll
                for (int nf = 0; nf < 4; nf++)
                    mma16816h(pacc[mf][nf], ah[mf], &bf[nf * 2]);
        }
        __syncthreads();            // all X reads done before overwriting with partials
        float* pk = partP + kq * 2176;
#pragma unroll
        for (int mf = 0; mf < 2; mf++)
#pragma unroll
            for (int nf = 0; nf < 4; nf++) {
                int col = nh * 32 + nf * 8 + kb;
                int row = mf * 16 + gid;
                *(float2*)(pk + row * 68 + col)       = make_float2(pacc[mf][nf][0], pacc[mf][nf][1]);
                *(float2*)(pk + (row + 8) * 68 + col) = make_float2(pacc[mf][nf][2], pacc[mf][nf][3]);
            }
    };
    auto reduceP = [&](int buf) {   // partP + bsum -> Ps[buf] (caller syncs before)
        float* dst = (float*)(smc + OFF_PS) + buf * 2048;
#pragma unroll
        for (int half = 0; half < 2; half++) {
            int idx = tid + half * 256;
            int b = idx >> 4, jj = idx & 15;
            const float* pb = partP + b * 68 + jj * 4;
            float4 q0 = *(const float4*)(pb);
            float4 q1 = *(const float4*)(pb + 2176);
            float4 q2 = *(const float4*)(pb + 4352);
            float4 q3 = *(const float4*)(pb + 6528);
            float4 bv = *(const float4*)(bs + jj * 4);
            float4 o;
            o.x = q0.x + q1.x + q2.x + q3.x + bv.x;
            o.y = q0.y + q1.y + q2.y + q3.y + bv.y;
            o.z = q0.z + q1.z + q2.z + q3.z + bv.z;
            o.w = q0.w + q1.w + q2.w + q3.w + bv.w;
            *(float4*)(dst + b * 64 + jj * 4) = o;
        }
    };

    // ---- prologue: P(0) -> Ps[0] ----
    load_X(0);
    cpa_wait0();
    __syncthreads();
    pmma_store();
    __syncthreads();
    reduceP(0);
    __syncthreads();

    for (int t = 0; t < TSTEPS; t++) {
        const __half* hsrc = g_h2 + (size_t)(t & 1) * (BATCH * HDIM);
        __half* hdst = g_h2 + (size_t)((t + 1) & 1) * (BATCH * HDIM);

        // ---- fine-grained wait (acquire): this warp's h quarter ready ----
        if (lane == 0) {
            unsigned tgt = 16u * (unsigned)t;
            while (ldacq(&g_cnt[grp_c][0]) < tgt) { }
        }
        __syncwarp();

        // ---- issue X(t+1) [G1], then h quarter 2 chunks [G2,G3] ----
        load_X((t + 1 < TSTEPS) ? (t + 1) : 0);
#pragma unroll
        for (int ck = 0; ck < 2; ck++) {
#pragma unroll
            for (int it = 0; it < 8; it++) {
                int idx = it * 32 + lane;         // 0..255
                int r = nh * 16 + (idx >> 4), ch = (idx & 15) + ck * 16;
                cpa16(smc + OFF_H + (size_t)r * 2064 + (size_t)(kq * 512 + ch * 16),
                      hsrc + (size_t)(b0 + r) * HDIM + kq * 256 + ch * 8);
            }
            cpa_commit();
        }

        // ---- X ready -> P(t+1) MMA fills the h-latency window ----
        cpa_wait2();
        __syncthreads();
        pmma_store();

        float acc[2][4][4];
#pragma unroll
        for (int a = 0; a < 2; a++)
#pragma unroll
            for (int b = 0; b < 4; b++)
#pragma unroll
                for (int q = 0; q < 4; q++) acc[a][b][q] = 0.0f;

        // ---- h chunk0 ready -> gate MMA kf 0..7 ----
        cpa_wait1();
        asm volatile("bar.sync %0, 64;" :: "r"(1 + kq) : "memory");
#pragma unroll
        for (int kf = 0; kf < 8; kf++) {
            uint32_t koff = (uint32_t)(kq * 256 + kf * 16) * 2;
            uint32_t ah[2][4];
            ldsm4(ah[0], sAB + koff);
            ldsm4(ah[1], sAB + 16u * 2064 + koff);
#pragma unroll
            for (int mf = 0; mf < 2; mf++)
#pragma unroll
                for (int nf = 0; nf < 4; nf++)
                    mma16816h(acc[mf][nf], ah[mf], &Breg[kf][nf * 2]);
        }
        // ---- h chunk1 ready -> gate MMA kf 8..15 ----
        cpa_wait0();
        asm volatile("bar.sync %0, 64;" :: "r"(1 + kq) : "memory");
#pragma unroll
        for (int kf = 8; kf < 16; kf++) {
            uint32_t koff = (uint32_t)(kq * 256 + kf * 16) * 2;
            uint32_t ah[2][4];
            ldsm4(ah[0], sAB + koff);
            ldsm4(ah[1], sAB + 16u * 2064 + koff);
#pragma unroll
            for (int mf = 0; mf < 2; mf++)
#pragma unroll
                for (int nf = 0; nf < 4; nf++)
                    mma16816h(acc[mf][nf], ah[mf], &Breg[kf][nf * 2]);
        }

        // ---- store gate partials ----
        {
            float* pk = part + kq * 2176;
#pragma unroll
            for (int mf = 0; mf < 2; mf++)
#pragma unroll
                for (int nf = 0; nf < 4; nf++) {
                    int col = nh * 32 + nf * 8 + kb;
                    int row = mf * 16 + gid;
                    *(float2*)(pk + row * 68 + col)       = make_float2(acc[mf][nf][0], acc[mf][nf][1]);
                    *(float2*)(pk + (row + 8) * 68 + col) = make_float2(acc[mf][nf][2], acc[mf][nf][3]);
                }
        }
        __syncthreads();

        // ---- cell (gate partials + Ps[t&1]); MUFU-packed ----
        const float* Ps = (const float*)(smc + OFF_PS) + (t & 1) * 2048;
        float G[2][4];
#pragma unroll
        for (int half = 0; half < 2; half++) {
            int idx = tid + half * 256;
            int b = idx >> 4, jj = idx & 15;
            const float* pb = part + b * 68 + jj * 4;
            float4 s0 = *(const float4*)(pb);
            float4 s1 = *(const float4*)(pb + 2176);
            float4 s2 = *(const float4*)(pb + 4352);
            float4 s3 = *(const float4*)(pb + 6528);
            float4 pv = *(const float4*)(Ps + b * 64 + jj * 4);
            G[half][0] = fminf(fmaxf(s0.x + s1.x + s2.x + s3.x + pv.x, -11.0f), 11.0f);
            G[half][1] = fminf(fmaxf(s0.y + s1.y + s2.y + s3.y + pv.y, -11.0f), 11.0f);
            G[half][2] = fminf(fmaxf(s0.z + s1.z + s2.z + s3.z + pv.z, -15.0f), 15.0f);
            G[half][3] = fminf(fmaxf(s0.w + s1.w + s2.w + s3.w + pv.w, -11.0f), 11.0f);
        }
        __half2 pif0 = __floats2half2_rn(-G[0][0] * L2E, -G[0][1] * L2E);
        __half2 pif1 = __floats2half2_rn(-G[1][0] * L2E, -G[1][1] * L2E);
        __half2 poo  = __floats2half2_rn(-G[0][3] * L2E, -G[1][3] * L2E);
        __half2 eif0; *(uint32_t*)&eif0 = ex2h2(*(uint32_t*)&pif0);
        __half2 eif1; *(uint32_t*)&eif1 = ex2h2(*(uint32_t*)&pif1);
        __half2 eoo;  *(uint32_t*)&eoo  = ex2h2(*(uint32_t*)&poo);
        float eiA[2] = { __low2float(eif0),  __low2float(eif1) };
        float efA[2] = { __high2float(eif0), __high2float(eif1) };
        float eoA[2] = { __low2float(eoo),   __high2float(eoo) };

        float pstash[2];
#pragma unroll
        for (int half = 0; half < 2; half++) {
            int idx = tid + half * 256;
            int b = idx >> 4;
            float eg = ex2f(G[half][2] * L2E2);
            float d1 = 1.0f + eiA[half], d2 = 1.0f + efA[half], d3 = 1.0f + eoA[half];
            float dg = eg + 1.0f;
            float m12 = d1 * d2, m23 = d2 * d3, m13 = d1 * d3;
            float m123 = m12 * d3;
            float r = rcpf(m123 * dg);
            float rdg = r * dg;
            float si = rdg * m23, sf = rdg * m13, so = rdg * m12;
            float tg = (eg - 1.0f) * (r * m123);
            float c = sf * c_reg[half] + si * tg;
            c_reg[half] = c;
            float ac = fminf(fmaxf(c * L2E2, -60.0f), 60.0f);
            float ec = ex2f(ac);
            float tc = (ec - 1.0f) * rcpf(ec + 1.0f);
            float h = so * tc;
            int jj = idx & 15;
            hdst[(size_t)(b0 + b) * HDIM + j0 + jj] = __float2half_rn(h);
            pstash[half] = h * was_reg[half];
        }

        // ---- reduce P(t+1) partials into Ps[(t+1)&1] (pre-publish: keeps
        //      partP safe from next step's X overwrite) ----
        reduceP((t + 1) & 1);

        // ---- publish h(t+1): barrier happens-before + release RED ----
        __syncthreads();
        if (tid == 0)
            asm volatile("red.release.gpu.global.add.u32 [%0], %1;"
                         :: "l"(&g_cnt[grp_p][0]), "r"(1u) : "memory");

        if (t >= SEL_START) {
#pragma unroll
            for (int half = 0; half < 2; half++) {
                int idx = tid + half * 256;
                int b = idx >> 4;
                float p = pstash[half];
                p += __shfl_xor_sync(0xFFFFFFFFu, p, 8);
                p += __shfl_xor_sync(0xFFFFFFFFu, p, 4);
                p += __shfl_xor_sync(0xFFFFFFFFu, p, 2);
                p += __shfl_xor_sync(0xFFFFFFFFu, p, 1);
                if ((lane & 15) == 0)
                    atomicAdd(&out[(b0 + b) * SEL_COUNT + (t - SEL_START)], p);
            }
        }
    }
}

// ---------------- launch ----------------
extern "C" void kernel_launch(void* const* d_in, const int* in_sizes, int n_in,
                              void* d_out, int out_size) {
    (void)in_sizes; (void)n_in; (void)out_size;
    const void*  prob  = d_in[0];
    const float* table = (const float*)d_in[2];
    const float* w_ih  = (const float*)d_in[3];
    const float* w_hh  = (const float*)d_in[4];
    const float* b_ih  = (const float*)d_in[5];
    const float* b_hh  = (const float*)d_in[6];
    const float* w_ans = (const float*)d_in[7];
    const float* b_ans = (const float*)d_in[8];
    const float* h0    = (const float*)d_in[9];
    const float* c0    = (const float*)d_in[10];
    float* out = (float*)d_out;

    static bool inited = false;
    if (!inited) {
        cudaFuncSetAttribute(lstm_persist, cudaFuncAttributeMaxDynamicSharedMemorySize, SMEM_PERSIST);
        inited = true;
    }

    fused_init<<<69, 1024>>>((const int*)prob, h0, out, b_ans);
    prep_all<<<2 * NG + (TSTEPS * BATCH + 1) / 2, 256>>>(prob, table, w_ih, w_hh, b_ih, b_hh);
    lstm_persist<<<NCTA, 256, SMEM_PERSIST>>>(c0, w_ans, out);
}